// round 1
// baseline (speedup 1.0000x reference)
#include <cuda_runtime.h>
#include <math.h>

#define S_LEN 4096
#define IN_DIM 1024
#define NODE 512
#define NH 8
#define HD 64

// Scratch (device globals: allocation is forbidden)
__device__ float g_QKV[3 * S_LEN * NODE];   // [3][S][NODE]  (Q,K,V)
__device__ float g_O[NH * S_LEN * HD];      // flat [H][S][D]
__device__ float g_aug[S_LEN * NODE];       // pre-layernorm

// ---------------------------------------------------------------------------
// C[M,N] = A[M,K] @ B[N,K]^T + bias[n]  (+ optional residual)
// 128x128 tile, BK=8, 256 threads, 8x8 microtile
// ---------------------------------------------------------------------------
__global__ __launch_bounds__(256)
void gemm128(const float* __restrict__ A, int lda,
             const float* __restrict__ B, int ldb, int K,
             const float* __restrict__ bias,
             const float* __restrict__ resid, int ldr,
             float* __restrict__ C, int ldc)
{
    __shared__ float As[8][132];
    __shared__ float Bs[8][132];
    const int tid = threadIdx.x;
    const int tx = tid & 15, ty = tid >> 4;
    const int m0 = blockIdx.y * 128, n0 = blockIdx.x * 128;
    const int lr = tid >> 1;           // 0..127
    const int lk = (tid & 1) * 4;      // 0 or 4
    const float* Ag = A + (m0 + lr) * lda + lk;
    const float* Bg = B + (n0 + lr) * ldb + lk;

    float acc[8][8];
#pragma unroll
    for (int i = 0; i < 8; i++)
#pragma unroll
        for (int j = 0; j < 8; j++) acc[i][j] = 0.f;

    for (int k0 = 0; k0 < K; k0 += 8) {
        float4 av = *(const float4*)(Ag + k0);
        float4 bv = *(const float4*)(Bg + k0);
        As[lk + 0][lr] = av.x; As[lk + 1][lr] = av.y;
        As[lk + 2][lr] = av.z; As[lk + 3][lr] = av.w;
        Bs[lk + 0][lr] = bv.x; Bs[lk + 1][lr] = bv.y;
        Bs[lk + 2][lr] = bv.z; Bs[lk + 3][lr] = bv.w;
        __syncthreads();
#pragma unroll
        for (int kk = 0; kk < 8; kk++) {
            float a[8], b[8];
            *(float4*)&a[0] = *(const float4*)&As[kk][ty * 8];
            *(float4*)&a[4] = *(const float4*)&As[kk][ty * 8 + 4];
            *(float4*)&b[0] = *(const float4*)&Bs[kk][tx * 8];
            *(float4*)&b[4] = *(const float4*)&Bs[kk][tx * 8 + 4];
#pragma unroll
            for (int i = 0; i < 8; i++)
#pragma unroll
                for (int j = 0; j < 8; j++)
                    acc[i][j] += a[i] * b[j];
        }
        __syncthreads();
    }

    const bool hasR = (resid != nullptr);
#pragma unroll
    for (int i = 0; i < 8; i++) {
        const int m = m0 + ty * 8 + i;
#pragma unroll
        for (int j4 = 0; j4 < 8; j4 += 4) {
            const int n = n0 + tx * 8 + j4;
            float4 bb = *(const float4*)&bias[n];
            float4 o;
            o.x = acc[i][j4 + 0] + bb.x;
            o.y = acc[i][j4 + 1] + bb.y;
            o.z = acc[i][j4 + 2] + bb.z;
            o.w = acc[i][j4 + 3] + bb.w;
            if (hasR) {
                float4 rr = *(const float4*)&resid[m * ldr + n];
                o.x += rr.x; o.y += rr.y; o.z += rr.z; o.w += rr.w;
            }
            *(float4*)&C[m * ldc + n] = o;
        }
    }
}

// ---------------------------------------------------------------------------
// Flash attention with multiplicative contact mask.
// grid = (S/64 q-tiles, H heads), block = 256 (16x16), 4x4 microtiles with
// strided (lane + 16*k) mapping, 65-float padded smem rows (conflict-free).
// Writes O in flat [H][S][D] order (matches the reference's scrambled reshape).
// ---------------------------------------------------------------------------
__global__ __launch_bounds__(256)
void attn_kernel(const float* __restrict__ qkv,
                 const float* __restrict__ contact,
                 const float* __restrict__ Wc,
                 float* __restrict__ O)
{
    extern __shared__ float sm[];
    float* Qs = sm;               // [64][65]
    float* Ks = sm + 64 * 65;     // [64][65]
    float* Vs = sm + 2 * 64 * 65; // [64][65]
    float* Ps = sm + 3 * 64 * 65; // [64][65]

    const int tid = threadIdx.x;
    const int tx = tid & 15, ty = tid >> 4;
    const int h = blockIdx.y;
    const int q0 = blockIdx.x * 64;

    const float* Qp = qkv;
    const float* Kp = qkv + S_LEN * NODE;
    const float* Vp = qkv + 2 * S_LEN * NODE;
    const float scale = 0.125f * Wc[h];   // 1/sqrt(64) * Wc[h]

    // load Q tile (coalesced float4 reads, scalar smem stores)
#pragma unroll
    for (int r = 0; r < 4; r++) {
        int idx = tid + 256 * r;
        int i = idx >> 4;
        int d4 = (idx & 15) << 2;
        float4 v = *(const float4*)&Qp[(q0 + i) * NODE + h * HD + d4];
        Qs[i * 65 + d4 + 0] = v.x; Qs[i * 65 + d4 + 1] = v.y;
        Qs[i * 65 + d4 + 2] = v.z; Qs[i * 65 + d4 + 3] = v.w;
    }

    float m[4], l[4], acc[4][4];
#pragma unroll
    for (int ii = 0; ii < 4; ii++) {
        m[ii] = -1e30f; l[ii] = 0.f;
#pragma unroll
        for (int dd = 0; dd < 4; dd++) acc[ii][dd] = 0.f;
    }

    for (int kb = 0; kb < S_LEN / 64; kb++) {
        const int k0 = kb * 64;
        __syncthreads();   // previous PV done before overwriting K/V
#pragma unroll
        for (int r = 0; r < 4; r++) {
            int idx = tid + 256 * r;
            int i = idx >> 4;
            int d4 = (idx & 15) << 2;
            float4 kv = *(const float4*)&Kp[(k0 + i) * NODE + h * HD + d4];
            float4 vv = *(const float4*)&Vp[(k0 + i) * NODE + h * HD + d4];
            Ks[i * 65 + d4 + 0] = kv.x; Ks[i * 65 + d4 + 1] = kv.y;
            Ks[i * 65 + d4 + 2] = kv.z; Ks[i * 65 + d4 + 3] = kv.w;
            Vs[i * 65 + d4 + 0] = vv.x; Vs[i * 65 + d4 + 1] = vv.y;
            Vs[i * 65 + d4 + 2] = vv.z; Vs[i * 65 + d4 + 3] = vv.w;
        }
        __syncthreads();

        // ---- S = Q K^T (rows ty+16*ii, cols tx+16*jj) ----
        float s[4][4];
#pragma unroll
        for (int ii = 0; ii < 4; ii++)
#pragma unroll
            for (int jj = 0; jj < 4; jj++) s[ii][jj] = 0.f;

#pragma unroll 8
        for (int d = 0; d < 64; d++) {
            float rq[4], rk[4];
#pragma unroll
            for (int ii = 0; ii < 4; ii++) rq[ii] = Qs[(ty + 16 * ii) * 65 + d];
#pragma unroll
            for (int jj = 0; jj < 4; jj++) rk[jj] = Ks[(tx + 16 * jj) * 65 + d];
#pragma unroll
            for (int ii = 0; ii < 4; ii++)
#pragma unroll
                for (int jj = 0; jj < 4; jj++)
                    s[ii][jj] += rq[ii] * rk[jj];
        }

        // ---- scale by (1/sqrt(D)) * Wc[h] * contact ----
#pragma unroll
        for (int ii = 0; ii < 4; ii++) {
            const float* crow = &contact[(q0 + ty + 16 * ii) * S_LEN + k0 + tx];
#pragma unroll
            for (int jj = 0; jj < 4; jj++)
                s[ii][jj] *= scale * crow[16 * jj];
        }

        // ---- online softmax (row stats reduced over the 16 tx lanes) ----
#pragma unroll
        for (int ii = 0; ii < 4; ii++) {
            float mx = fmaxf(fmaxf(s[ii][0], s[ii][1]), fmaxf(s[ii][2], s[ii][3]));
#pragma unroll
            for (int off = 8; off >= 1; off >>= 1)
                mx = fmaxf(mx, __shfl_xor_sync(0xffffffffu, mx, off));
            const float mnew = fmaxf(m[ii], mx);
            const float alpha = __expf(m[ii] - mnew);
            float rs = 0.f;
#pragma unroll
            for (int jj = 0; jj < 4; jj++) {
                s[ii][jj] = __expf(s[ii][jj] - mnew);
                rs += s[ii][jj];
            }
#pragma unroll
            for (int off = 8; off >= 1; off >>= 1)
                rs += __shfl_xor_sync(0xffffffffu, rs, off);
            l[ii] = l[ii] * alpha + rs;
            m[ii] = mnew;
#pragma unroll
            for (int dd = 0; dd < 4; dd++) acc[ii][dd] *= alpha;
#pragma unroll
            for (int jj = 0; jj < 4; jj++)
                Ps[(ty + 16 * ii) * 65 + tx + 16 * jj] = s[ii][jj];
        }
        __syncthreads();

        // ---- O += P @ V  (cols d = tx + 16*dd) ----
#pragma unroll 8
        for (int j = 0; j < 64; j++) {
            float rv[4], rp[4];
#pragma unroll
            for (int dd = 0; dd < 4; dd++) rv[dd] = Vs[j * 65 + tx + 16 * dd];
#pragma unroll
            for (int ii = 0; ii < 4; ii++) rp[ii] = Ps[(ty + 16 * ii) * 65 + j];
#pragma unroll
            for (int ii = 0; ii < 4; ii++)
#pragma unroll
                for (int dd = 0; dd < 4; dd++)
                    acc[ii][dd] += rp[ii] * rv[dd];
        }
    }

    // ---- normalize + write flat [H][S][D] ----
#pragma unroll
    for (int ii = 0; ii < 4; ii++) {
        const float inv = 1.f / l[ii];
#pragma unroll
        for (int dd = 0; dd < 4; dd++)
            O[h * S_LEN * HD + (q0 + ty + 16 * ii) * HD + tx + 16 * dd] =
                acc[ii][dd] * inv;
    }
}

// ---------------------------------------------------------------------------
// LayerNorm: one block per row (512 elems), two-pass, 256 threads x float2
// ---------------------------------------------------------------------------
__global__ __launch_bounds__(256)
void ln_kernel(const float* __restrict__ x,
               const float* __restrict__ gamma,
               const float* __restrict__ beta,
               float* __restrict__ out)
{
    __shared__ float red[16];
    const int row = blockIdx.x;
    const int tid = threadIdx.x;
    const float* xr = x + row * NODE;
    float2 v = *(const float2*)&xr[tid * 2];

    float ssum = v.x + v.y;
#pragma unroll
    for (int off = 16; off >= 1; off >>= 1)
        ssum += __shfl_xor_sync(0xffffffffu, ssum, off);
    if ((tid & 31) == 0) red[tid >> 5] = ssum;
    __syncthreads();
    float tot = 0.f;
#pragma unroll
    for (int w = 0; w < 8; w++) tot += red[w];
    const float mean = tot * (1.f / NODE);

    const float dx = v.x - mean, dy = v.y - mean;
    float sq = dx * dx + dy * dy;
#pragma unroll
    for (int off = 16; off >= 1; off >>= 1)
        sq += __shfl_xor_sync(0xffffffffu, sq, off);
    if ((tid & 31) == 0) red[8 + (tid >> 5)] = sq;
    __syncthreads();
    float tot2 = 0.f;
#pragma unroll
    for (int w = 0; w < 8; w++) tot2 += red[8 + w];
    const float inv = rsqrtf(tot2 * (1.f / NODE) + 1e-5f);

    const int n = tid * 2;
    float2 g = *(const float2*)&gamma[n];
    float2 b = *(const float2*)&beta[n];
    float2 o;
    o.x = dx * inv * g.x + b.x;
    o.y = dy * inv * g.y + b.y;
    *(float2*)&out[row * NODE + n] = o;
}

// ---------------------------------------------------------------------------
extern "C" void kernel_launch(void* const* d_in, const int* in_sizes, int n_in,
                              void* d_out, int out_size)
{
    const float* X     = (const float*)d_in[0];
    const float* Ct    = (const float*)d_in[1];
    const float* Wq    = (const float*)d_in[2];
    const float* bq    = (const float*)d_in[3];
    const float* Wk    = (const float*)d_in[4];
    const float* bk    = (const float*)d_in[5];
    const float* Wv    = (const float*)d_in[6];
    const float* bv    = (const float*)d_in[7];
    const float* Wc    = (const float*)d_in[8];
    const float* Wo    = (const float*)d_in[9];
    const float* bo    = (const float*)d_in[10];
    const float* gamma = (const float*)d_in[11];
    const float* beta  = (const float*)d_in[12];
    float* out = (float*)d_out;

    void *pQKV, *pO, *pAug;
    cudaGetSymbolAddress(&pQKV, g_QKV);
    cudaGetSymbolAddress(&pO, g_O);
    cudaGetSymbolAddress(&pAug, g_aug);
    float* qkv = (float*)pQKV;
    float* Obuf = (float*)pO;
    float* aug = (float*)pAug;

    dim3 gg(NODE / 128, S_LEN / 128);   // (4, 32)
    dim3 bb(256);

    // QKV projections
    gemm128<<<gg, bb>>>(X, IN_DIM, Wq, IN_DIM, IN_DIM, bq, nullptr, 0,
                        qkv, NODE);
    gemm128<<<gg, bb>>>(X, IN_DIM, Wk, IN_DIM, IN_DIM, bk, nullptr, 0,
                        qkv + S_LEN * NODE, NODE);
    gemm128<<<gg, bb>>>(X, IN_DIM, Wv, IN_DIM, IN_DIM, bv, nullptr, 0,
                        qkv + 2 * S_LEN * NODE, NODE);

    // Flash attention with contact mask
    const int smem_bytes = 4 * 64 * 65 * (int)sizeof(float);  // 66560
    cudaFuncSetAttribute(attn_kernel,
                         cudaFuncAttributeMaxDynamicSharedMemorySize,
                         smem_bytes);
    attn_kernel<<<dim3(S_LEN / 64, NH), bb, smem_bytes>>>(qkv, Ct, Wc, Obuf);

    // Output projection + bias + residual (X[:, :NODE])
    gemm128<<<gg, bb>>>(Obuf, NODE, Wo, NODE, NODE, bo, X, IN_DIM,
                        aug, NODE);

    // LayerNorm
    ln_kernel<<<S_LEN, 256>>>(aug, gamma, beta, out);
}

// round 2
// speedup vs baseline: 4.3791x; 4.3791x over previous
#include <cuda_runtime.h>
#include <cuda_bf16.h>
#include <math.h>

#define S_LEN 4096
#define IN_DIM 1024
#define NODE 512
#define NH 8
#define HD 64

typedef __nv_bfloat16 bf16;
typedef __nv_bfloat162 bf162;

// ---------------- device scratch (no allocation allowed) -------------------
__device__ bf16  g_Xbf[S_LEN * IN_DIM];
__device__ bf16  g_Wqb[NODE * IN_DIM];
__device__ bf16  g_Wkb[NODE * IN_DIM];
__device__ bf16  g_Wvb[NODE * IN_DIM];
__device__ bf16  g_Wob[NODE * NODE];
__device__ bf16  g_QKVb[3 * S_LEN * NODE];   // Q,K,V bf16 [3][S][512]
__device__ bf16  g_Obf[NH * S_LEN * HD];     // attention out, flat [H][S][D]
__device__ float g_aug[S_LEN * NODE];        // pre-layernorm fp32

// ---------------------------------------------------------------------------
__device__ __forceinline__ void mma16816(float c[4], const unsigned a[4],
                                         unsigned b0, unsigned b1) {
    asm volatile(
        "mma.sync.aligned.m16n8k16.row.col.f32.bf16.bf16.f32 "
        "{%0,%1,%2,%3}, {%4,%5,%6,%7}, {%8,%9}, {%0,%1,%2,%3};\n"
        : "+f"(c[0]), "+f"(c[1]), "+f"(c[2]), "+f"(c[3])
        : "r"(a[0]), "r"(a[1]), "r"(a[2]), "r"(a[3]), "r"(b0), "r"(b1));
}

__device__ __forceinline__ unsigned pack_bf16(float x, float y) {
    bf162 h = __float22bfloat162_rn(make_float2(x, y));
    return *(unsigned*)&h;
}

// ---------------------------------------------------------------------------
// fp32 -> bf16 elementwise
// ---------------------------------------------------------------------------
__global__ __launch_bounds__(256)
void cvt_bf16(const float* __restrict__ src, bf16* __restrict__ dst, int n)
{
    int i = (blockIdx.x * 256 + threadIdx.x) * 4;
    if (i + 3 < n) {
        float4 v = *(const float4*)&src[i];
        bf162 h0 = __float22bfloat162_rn(make_float2(v.x, v.y));
        bf162 h1 = __float22bfloat162_rn(make_float2(v.z, v.w));
        uint2 o;
        o.x = *(unsigned*)&h0;
        o.y = *(unsigned*)&h1;
        *(uint2*)&dst[i] = o;
    }
}

// ---------------------------------------------------------------------------
// bf16 tensor-core GEMM: C[M,N] = A[M,K] @ B[N,K]^T + bias (+resid)
// 128x128 tile, BK=32, 256 threads (8 warps in 2x4), m16n8k16 mma.
// z selects {B0/B1/B2, bias0/1/2, Cb0/1/2} (fused QKV). If Cf!=null, fp32
// output with optional residual; else bf16 output to Cb[z].
// ---------------------------------------------------------------------------
__global__ __launch_bounds__(256)
void gemm_bf16(const bf16* __restrict__ A, int lda,
               const bf16* __restrict__ B0, const bf16* __restrict__ B1,
               const bf16* __restrict__ B2, int ldb, int K,
               const float* __restrict__ bias0, const float* __restrict__ bias1,
               const float* __restrict__ bias2,
               const float* __restrict__ resid, int ldr,
               float* __restrict__ Cf,
               bf16* __restrict__ Cb0, bf16* __restrict__ Cb1,
               bf16* __restrict__ Cb2, int ldc)
{
    const int z = blockIdx.z;
    const bf16* B = (z == 0) ? B0 : (z == 1) ? B1 : B2;
    const float* bias = (z == 0) ? bias0 : (z == 1) ? bias1 : bias2;
    bf16* Cb = (z == 0) ? Cb0 : (z == 1) ? Cb1 : Cb2;

    __shared__ bf16 As[128][40];   // stride 40 halves = 20 u32 (conflict-free)
    __shared__ bf16 Bs[128][40];
    const unsigned* As32 = (const unsigned*)&As[0][0];
    const unsigned* Bs32 = (const unsigned*)&Bs[0][0];

    const int tid = threadIdx.x;
    const int lane = tid & 31, wid = tid >> 5;
    const int g = lane >> 2, t = lane & 3;
    const int wm = wid >> 2, wn = wid & 3;       // 2 x 4 warp grid
    const int rm = wm * 64, rn = wn * 32;
    const int m0 = blockIdx.y * 128, n0 = blockIdx.x * 128;

    // fill mapping: 2 uint4 (16 halves) per thread per tile
    const int frow = tid >> 2;          // 0..63  (row pairs: frow, frow+64)
    const int fc = (tid & 3);           // uint4 within row half? -> use idx math

    float acc[4][4][4];
#pragma unroll
    for (int a = 0; a < 4; a++)
#pragma unroll
        for (int b = 0; b < 4; b++)
#pragma unroll
            for (int c = 0; c < 4; c++) acc[a][b][c] = 0.f;

    const int nk = K / 32;
    uint4 pa[2], pb[2];
#pragma unroll
    for (int r = 0; r < 2; r++) {
        int idx = tid + 256 * r;          // 0..511
        int row = idx >> 2, c = idx & 3;  // 4 uint4 per 32-half row
        pa[r] = *(const uint4*)&A[(size_t)(m0 + row) * lda + c * 8];
        pb[r] = *(const uint4*)&B[(size_t)(n0 + row) * ldb + c * 8];
    }

    for (int kt = 0; kt < nk; kt++) {
#pragma unroll
        for (int r = 0; r < 2; r++) {
            int idx = tid + 256 * r;
            int row = idx >> 2, c = idx & 3;
            *(uint4*)&As[row][c * 8] = pa[r];
            *(uint4*)&Bs[row][c * 8] = pb[r];
        }
        __syncthreads();
        if (kt + 1 < nk) {
            int k0 = (kt + 1) * 32;
#pragma unroll
            for (int r = 0; r < 2; r++) {
                int idx = tid + 256 * r;
                int row = idx >> 2, c = idx & 3;
                pa[r] = *(const uint4*)&A[(size_t)(m0 + row) * lda + k0 + c * 8];
                pb[r] = *(const uint4*)&B[(size_t)(n0 + row) * ldb + k0 + c * 8];
            }
        }
#pragma unroll
        for (int ks = 0; ks < 2; ks++) {
            unsigned afr[4][4];
#pragma unroll
            for (int mf = 0; mf < 4; mf++) {
                int base = (rm + mf * 16 + g) * 20 + ks * 8 + t;
                afr[mf][0] = As32[base];
                afr[mf][1] = As32[base + 160];
                afr[mf][2] = As32[base + 4];
                afr[mf][3] = As32[base + 164];
            }
#pragma unroll
            for (int nf = 0; nf < 4; nf++) {
                int bbase = (rn + nf * 8 + g) * 20 + ks * 8 + t;
                unsigned b0 = Bs32[bbase];
                unsigned b1 = Bs32[bbase + 4];
#pragma unroll
                for (int mf = 0; mf < 4; mf++)
                    mma16816(acc[mf][nf], afr[mf], b0, b1);
            }
        }
        __syncthreads();
    }
    (void)frow; (void)fc;

    // epilogue
#pragma unroll
    for (int mf = 0; mf < 4; mf++) {
        const int m = m0 + rm + mf * 16 + g;
#pragma unroll
        for (int nf = 0; nf < 4; nf++) {
            const int n = n0 + rn + nf * 8 + 2 * t;
            float2 bb = *(const float2*)&bias[n];
            float v0 = acc[mf][nf][0] + bb.x;
            float v1 = acc[mf][nf][1] + bb.y;
            float v2 = acc[mf][nf][2] + bb.x;
            float v3 = acc[mf][nf][3] + bb.y;
            if (Cf) {
                float2 r0 = *(const float2*)&resid[(size_t)m * ldr + n];
                float2 r1 = *(const float2*)&resid[(size_t)(m + 8) * ldr + n];
                float2 o0 = make_float2(v0 + r0.x, v1 + r0.y);
                float2 o1 = make_float2(v2 + r1.x, v3 + r1.y);
                *(float2*)&Cf[(size_t)m * ldc + n] = o0;
                *(float2*)&Cf[(size_t)(m + 8) * ldc + n] = o1;
            } else {
                *(unsigned*)&Cb[(size_t)m * ldc + n] = pack_bf16(v0, v1);
                *(unsigned*)&Cb[(size_t)(m + 8) * ldc + n] = pack_bf16(v2, v3);
            }
        }
    }
}

// ---------------------------------------------------------------------------
// Flash attention (bf16 mma) with multiplicative contact mask.
// CTA: 128 q-rows x one head, 8 warps (16 rows each), 64-key blocks.
// Smem strides: 72 halves = 36 u32  => all fragment loads conflict-free.
// ---------------------------------------------------------------------------
__global__ __launch_bounds__(256)
void attn_mma(const bf16* __restrict__ qkv,
              const float* __restrict__ contact,
              const float* __restrict__ Wc,
              bf16* __restrict__ O)
{
    extern __shared__ bf16 sm[];
    bf16* Qs = sm;                   // [128][72]
    bf16* Ks = sm + 128 * 72;        // [64][72]
    bf16* Vt = Ks + 64 * 72;         // [64][72]  (Vt[d][key])
    bf16* Ps = Vt + 64 * 72;         // [128][72]
    const unsigned* Qs32 = (const unsigned*)Qs;
    const unsigned* Ks32 = (const unsigned*)Ks;
    const unsigned* Vt32 = (const unsigned*)Vt;
    unsigned* Ps32 = (unsigned*)Ps;

    const int tid = threadIdx.x;
    const int lane = tid & 31, wid = tid >> 5;
    const int g = lane >> 2, t = lane & 3;
    const int h = blockIdx.y;
    const int q0 = blockIdx.x * 128;
    const int wr0 = wid * 16;

    const bf16* Qp = qkv;
    const bf16* Kp = qkv + (size_t)S_LEN * NODE;
    const bf16* Vp = qkv + 2 * (size_t)S_LEN * NODE;
    const float scale = 0.125f * Wc[h];

    // ---- Q tile fill (128 x 64 halves) ----
#pragma unroll
    for (int r = 0; r < 4; r++) {
        int idx = tid + 256 * r;          // 0..1023
        int row = idx >> 3, c = idx & 7;  // 8 uint4 per 64-half row
        uint4 v = *(const uint4*)&Qp[(size_t)(q0 + row) * NODE + h * HD + c * 8];
        *(uint4*)&Qs[row * 72 + c * 8] = v;
    }

    float m0r = -1e30f, m1r = -1e30f, l0 = 0.f, l1 = 0.f;
    float oc[8][4];
#pragma unroll
    for (int nf = 0; nf < 8; nf++)
#pragma unroll
        for (int j = 0; j < 4; j++) oc[nf][j] = 0.f;

    for (int kb = 0; kb < S_LEN / 64; kb++) {
        const int k0 = kb * 64;
        __syncthreads();   // prior PV done with Vt; Q fill visible on kb==0
#pragma unroll
        for (int r = 0; r < 2; r++) {
            int idx = tid + 256 * r;          // 0..511
            int key = idx >> 3, c = idx & 7;
            uint4 kv = *(const uint4*)&Kp[(size_t)(k0 + key) * NODE + h * HD + c * 8];
            *(uint4*)&Ks[key * 72 + c * 8] = kv;
            uint4 vv = *(const uint4*)&Vp[(size_t)(k0 + key) * NODE + h * HD + c * 8];
            bf16 tmp[8];
            *(uint4*)tmp = vv;
#pragma unroll
            for (int j = 0; j < 8; j++)
                Vt[(c * 8 + j) * 72 + key] = tmp[j];   // transpose to [d][key]
        }
        __syncthreads();

        // ---- S = Q K^T ----
        float sc[8][4];
#pragma unroll
        for (int nf = 0; nf < 8; nf++)
#pragma unroll
            for (int j = 0; j < 4; j++) sc[nf][j] = 0.f;

#pragma unroll
        for (int ks = 0; ks < 4; ks++) {
            unsigned afr[4];
            int base = (wr0 + g) * 36 + ks * 8 + t;
            afr[0] = Qs32[base];
            afr[1] = Qs32[base + 288];   // +8 rows * 36
            afr[2] = Qs32[base + 4];
            afr[3] = Qs32[base + 292];
#pragma unroll
            for (int nf = 0; nf < 8; nf++) {
                int bbase = (nf * 8 + g) * 36 + ks * 8 + t;
                mma16816(sc[nf], afr, Ks32[bbase], Ks32[bbase + 4]);
            }
        }

        // ---- contact mask * scale ----
        const float* cr0 = contact + (size_t)(q0 + wr0 + g) * S_LEN + k0;
        const float* cr1 = cr0 + 8 * (size_t)S_LEN;
#pragma unroll
        for (int nf = 0; nf < 8; nf++) {
            float2 c0 = *(const float2*)&cr0[nf * 8 + 2 * t];
            float2 c1 = *(const float2*)&cr1[nf * 8 + 2 * t];
            sc[nf][0] *= scale * c0.x;
            sc[nf][1] *= scale * c0.y;
            sc[nf][2] *= scale * c1.x;
            sc[nf][3] *= scale * c1.y;
        }

        // ---- online softmax (rows wr0+g and wr0+8+g) ----
        float mx0 = -1e30f, mx1 = -1e30f;
#pragma unroll
        for (int nf = 0; nf < 8; nf++) {
            mx0 = fmaxf(mx0, fmaxf(sc[nf][0], sc[nf][1]));
            mx1 = fmaxf(mx1, fmaxf(sc[nf][2], sc[nf][3]));
        }
        mx0 = fmaxf(mx0, __shfl_xor_sync(0xffffffffu, mx0, 1));
        mx0 = fmaxf(mx0, __shfl_xor_sync(0xffffffffu, mx0, 2));
        mx1 = fmaxf(mx1, __shfl_xor_sync(0xffffffffu, mx1, 1));
        mx1 = fmaxf(mx1, __shfl_xor_sync(0xffffffffu, mx1, 2));
        const float mn0 = fmaxf(m0r, mx0);
        const float mn1 = fmaxf(m1r, mx1);
        const float al0 = __expf(m0r - mn0);
        const float al1 = __expf(m1r - mn1);
        m0r = mn0; m1r = mn1;

        float rs0 = 0.f, rs1 = 0.f;
#pragma unroll
        for (int nf = 0; nf < 8; nf++) {
            sc[nf][0] = __expf(sc[nf][0] - mn0);
            sc[nf][1] = __expf(sc[nf][1] - mn0);
            sc[nf][2] = __expf(sc[nf][2] - mn1);
            sc[nf][3] = __expf(sc[nf][3] - mn1);
            rs0 += sc[nf][0] + sc[nf][1];
            rs1 += sc[nf][2] + sc[nf][3];
        }
        rs0 += __shfl_xor_sync(0xffffffffu, rs0, 1);
        rs0 += __shfl_xor_sync(0xffffffffu, rs0, 2);
        rs1 += __shfl_xor_sync(0xffffffffu, rs1, 1);
        rs1 += __shfl_xor_sync(0xffffffffu, rs1, 2);
        l0 = l0 * al0 + rs0;
        l1 = l1 * al1 + rs1;
#pragma unroll
        for (int nf = 0; nf < 8; nf++) {
            oc[nf][0] *= al0; oc[nf][1] *= al0;
            oc[nf][2] *= al1; oc[nf][3] *= al1;
        }

        // ---- P -> smem (warp-private rows) ----
#pragma unroll
        for (int nf = 0; nf < 8; nf++) {
            Ps32[(wr0 + g) * 36 + nf * 4 + t] = pack_bf16(sc[nf][0], sc[nf][1]);
            Ps32[(wr0 + 8 + g) * 36 + nf * 4 + t] = pack_bf16(sc[nf][2], sc[nf][3]);
        }
        __syncwarp();

        // ---- O += P V ----
#pragma unroll
        for (int ks = 0; ks < 4; ks++) {
            unsigned afr[4];
            int base = (wr0 + g) * 36 + ks * 8 + t;
            afr[0] = Ps32[base];
            afr[1] = Ps32[base + 288];
            afr[2] = Ps32[base + 4];
            afr[3] = Ps32[base + 292];
#pragma unroll
            for (int nf = 0; nf < 8; nf++) {
                int bbase = (nf * 8 + g) * 36 + ks * 8 + t;
                mma16816(oc[nf], afr, Vt32[bbase], Vt32[bbase + 4]);
            }
        }
        __syncwarp();   // PV reads of Ps done before next iteration's stores
    }

    // ---- normalize + store flat [H][S][D] bf16 ----
    const float inv0 = 1.f / l0;
    const float inv1 = 1.f / l1;
    const size_t ob = (size_t)h * S_LEN * HD;
#pragma unroll
    for (int nf = 0; nf < 8; nf++) {
        int col = nf * 8 + 2 * t;
        *(unsigned*)&O[ob + (size_t)(q0 + wr0 + g) * HD + col] =
            pack_bf16(oc[nf][0] * inv0, oc[nf][1] * inv0);
        *(unsigned*)&O[ob + (size_t)(q0 + wr0 + 8 + g) * HD + col] =
            pack_bf16(oc[nf][2] * inv1, oc[nf][3] * inv1);
    }
}

// ---------------------------------------------------------------------------
// LayerNorm: one block per row (512 elems), 256 threads x float2
// ---------------------------------------------------------------------------
__global__ __launch_bounds__(256)
void ln_kernel(const float* __restrict__ x,
               const float* __restrict__ gamma,
               const float* __restrict__ beta,
               float* __restrict__ out)
{
    __shared__ float red[16];
    const int row = blockIdx.x;
    const int tid = threadIdx.x;
    const float* xr = x + (size_t)row * NODE;
    float2 v = *(const float2*)&xr[tid * 2];

    float ssum = v.x + v.y;
#pragma unroll
    for (int off = 16; off >= 1; off >>= 1)
        ssum += __shfl_xor_sync(0xffffffffu, ssum, off);
    if ((tid & 31) == 0) red[tid >> 5] = ssum;
    __syncthreads();
    float tot = 0.f;
#pragma unroll
    for (int w = 0; w < 8; w++) tot += red[w];
    const float mean = tot * (1.f / NODE);

    const float dx = v.x - mean, dy = v.y - mean;
    float sq = dx * dx + dy * dy;
#pragma unroll
    for (int off = 16; off >= 1; off >>= 1)
        sq += __shfl_xor_sync(0xffffffffu, sq, off);
    if ((tid & 31) == 0) red[8 + (tid >> 5)] = sq;
    __syncthreads();
    float tot2 = 0.f;
#pragma unroll
    for (int w = 0; w < 8; w++) tot2 += red[8 + w];
    const float inv = rsqrtf(tot2 * (1.f / NODE) + 1e-5f);

    const int n = tid * 2;
    float2 gm = *(const float2*)&gamma[n];
    float2 bt = *(const float2*)&beta[n];
    float2 o;
    o.x = dx * inv * gm.x + bt.x;
    o.y = dy * inv * gm.y + bt.y;
    *(float2*)&out[(size_t)row * NODE + n] = o;
}

// ---------------------------------------------------------------------------
extern "C" void kernel_launch(void* const* d_in, const int* in_sizes, int n_in,
                              void* d_out, int out_size)
{
    const float* X     = (const float*)d_in[0];
    const float* Ct    = (const float*)d_in[1];
    const float* Wq    = (const float*)d_in[2];
    const float* bq    = (const float*)d_in[3];
    const float* Wk    = (const float*)d_in[4];
    const float* bk    = (const float*)d_in[5];
    const float* Wv    = (const float*)d_in[6];
    const float* bv    = (const float*)d_in[7];
    const float* Wc    = (const float*)d_in[8];
    const float* Wo    = (const float*)d_in[9];
    const float* bo    = (const float*)d_in[10];
    const float* gamma = (const float*)d_in[11];
    const float* beta  = (const float*)d_in[12];
    float* out = (float*)d_out;

    void *pX, *pWq, *pWk, *pWv, *pWo, *pQKV, *pO, *pAug;
    cudaGetSymbolAddress(&pX, g_Xbf);
    cudaGetSymbolAddress(&pWq, g_Wqb);
    cudaGetSymbolAddress(&pWk, g_Wkb);
    cudaGetSymbolAddress(&pWv, g_Wvb);
    cudaGetSymbolAddress(&pWo, g_Wob);
    cudaGetSymbolAddress(&pQKV, g_QKVb);
    cudaGetSymbolAddress(&pO, g_Obf);
    cudaGetSymbolAddress(&pAug, g_aug);
    bf16* Xbf = (bf16*)pX;
    bf16* Wqb = (bf16*)pWq;
    bf16* Wkb = (bf16*)pWk;
    bf16* Wvb = (bf16*)pWv;
    bf16* Wob = (bf16*)pWo;
    bf16* qkv = (bf16*)pQKV;
    bf16* Obf = (bf16*)pO;
    float* aug = (float*)pAug;

    // 1. fp32 -> bf16 conversions
    cvt_bf16<<<S_LEN * IN_DIM / 1024, 256>>>(X, Xbf, S_LEN * IN_DIM);
    cvt_bf16<<<NODE * IN_DIM / 1024, 256>>>(Wq, Wqb, NODE * IN_DIM);
    cvt_bf16<<<NODE * IN_DIM / 1024, 256>>>(Wk, Wkb, NODE * IN_DIM);
    cvt_bf16<<<NODE * IN_DIM / 1024, 256>>>(Wv, Wvb, NODE * IN_DIM);
    cvt_bf16<<<NODE * NODE / 1024, 256>>>(Wo, Wob, NODE * NODE);

    // 2. fused QKV projection (z = 0,1,2)
    gemm_bf16<<<dim3(NODE / 128, S_LEN / 128, 3), 256>>>(
        Xbf, IN_DIM, Wqb, Wkb, Wvb, IN_DIM, IN_DIM,
        bq, bk, bv, nullptr, 0, nullptr,
        qkv, qkv + (size_t)S_LEN * NODE, qkv + 2 * (size_t)S_LEN * NODE, NODE);

    // 3. flash attention with contact mask
    const int smem_bytes = (128 + 64 + 64 + 128) * 72 * (int)sizeof(bf16); // 55296
    cudaFuncSetAttribute(attn_mma,
                         cudaFuncAttributeMaxDynamicSharedMemorySize,
                         smem_bytes);
    attn_mma<<<dim3(S_LEN / 128, NH), 256, smem_bytes>>>(qkv, Ct, Wc, Obf);

    // 4. output projection + bias + residual (fp32 out)
    gemm_bf16<<<dim3(NODE / 128, S_LEN / 128, 1), 256>>>(
        Obf, NODE, Wob, Wob, Wob, NODE, NODE,
        bo, bo, bo, X, IN_DIM, aug,
        nullptr, nullptr, nullptr, NODE);

    // 5. LayerNorm
    ln_kernel<<<S_LEN, 256>>>(aug, gamma, beta, out);
}

// round 3
// speedup vs baseline: 6.8986x; 1.5753x over previous
#include <cuda_runtime.h>
#include <cuda_bf16.h>
#include <math.h>

#define S_LEN 4096
#define IN_DIM 1024
#define NODE 512
#define NH 8
#define HD 64
#define NKB (S_LEN / 64)

typedef __nv_bfloat16 bf16;
typedef __nv_bfloat162 bf162;

// ---------------- device scratch ----------------
__device__ bf16  g_Xbf[S_LEN * IN_DIM];
__device__ bf16  g_Wqb[NODE * IN_DIM];
__device__ bf16  g_Wkb[NODE * IN_DIM];
__device__ bf16  g_Wvb[NODE * IN_DIM];
__device__ bf16  g_Wob[NODE * NODE];
__device__ bf16  g_QKVb[3 * S_LEN * NODE];
__device__ bf16  g_Obf[NH * S_LEN * HD];
__device__ float g_aug[S_LEN * NODE];

// ---------------- helpers ----------------
__device__ __forceinline__ void mma16816(float c[4], const unsigned a[4],
                                         unsigned b0, unsigned b1) {
    asm volatile(
        "mma.sync.aligned.m16n8k16.row.col.f32.bf16.bf16.f32 "
        "{%0,%1,%2,%3}, {%4,%5,%6,%7}, {%8,%9}, {%0,%1,%2,%3};\n"
        : "+f"(c[0]), "+f"(c[1]), "+f"(c[2]), "+f"(c[3])
        : "r"(a[0]), "r"(a[1]), "r"(a[2]), "r"(a[3]), "r"(b0), "r"(b1));
}
__device__ __forceinline__ unsigned pack_bf16(float x, float y) {
    unsigned r;
    asm("cvt.rn.bf16x2.f32 %0, %1, %2;" : "=r"(r) : "f"(y), "f"(x));
    return r;
}
__device__ __forceinline__ float ex2(float x) {
    float y;
    asm("ex2.approx.f32 %0, %1;" : "=f"(y) : "f"(x));
    return y;
}
__device__ __forceinline__ unsigned sptr(const void* p) {
    return (unsigned)__cvta_generic_to_shared(p);
}
__device__ __forceinline__ void ldsm4(unsigned r[4], unsigned a) {
    asm volatile("ldmatrix.sync.aligned.m8n8.x4.shared.b16 {%0,%1,%2,%3}, [%4];\n"
                 : "=r"(r[0]), "=r"(r[1]), "=r"(r[2]), "=r"(r[3]) : "r"(a));
}
__device__ __forceinline__ void ldsm2(unsigned& r0, unsigned& r1, unsigned a) {
    asm volatile("ldmatrix.sync.aligned.m8n8.x2.shared.b16 {%0,%1}, [%2];\n"
                 : "=r"(r0), "=r"(r1) : "r"(a));
}
__device__ __forceinline__ void ldsm2t(unsigned& r0, unsigned& r1, unsigned a) {
    asm volatile("ldmatrix.sync.aligned.m8n8.x2.trans.shared.b16 {%0,%1}, [%2];\n"
                 : "=r"(r0), "=r"(r1) : "r"(a));
}
__device__ __forceinline__ void cpasync16(unsigned saddr, const void* g) {
    asm volatile("cp.async.cg.shared.global [%0], [%1], 16;\n"
                 :: "r"(saddr), "l"(g));
}
__device__ __forceinline__ void cpcommit() {
    asm volatile("cp.async.commit_group;\n");
}
__device__ __forceinline__ void cpwait0() {
    asm volatile("cp.async.wait_group 0;\n");
}

// ---------------------------------------------------------------------------
// fused fp32 -> bf16 conversions (X, Wq, Wk, Wv, Wo), 1024 elems per block
// blocks: X 4096 | Wq 512 | Wk 512 | Wv 512 | Wo 256  = 5888
// ---------------------------------------------------------------------------
__global__ __launch_bounds__(256)
void cvt_all(const float* __restrict__ X, const float* __restrict__ Wq,
             const float* __restrict__ Wk, const float* __restrict__ Wv,
             const float* __restrict__ Wo,
             bf16* dX, bf16* dWq, bf16* dWk, bf16* dWv, bf16* dWo)
{
    int b = blockIdx.x;
    const float* s; bf16* d; int off;
    if (b < 4096)      { s = X;  d = dX;  off = b; }
    else if (b < 4608) { s = Wq; d = dWq; off = b - 4096; }
    else if (b < 5120) { s = Wk; d = dWk; off = b - 4608; }
    else if (b < 5632) { s = Wv; d = dWv; off = b - 5120; }
    else               { s = Wo; d = dWo; off = b - 5632; }
    int i = (off * 256 + threadIdx.x) * 4;
    float4 v = *(const float4*)&s[i];
    uint2 o;
    o.x = pack_bf16(v.x, v.y);
    o.y = pack_bf16(v.z, v.w);
    *(uint2*)&d[i] = o;
}

// ---------------------------------------------------------------------------
// bf16 tensor-core GEMM with ldmatrix fragment loads.
// C[M,N] = A[M,K] @ B[N,K]^T + bias (+resid). 128x128, BK=32, 256 thr.
// ---------------------------------------------------------------------------
__global__ __launch_bounds__(256)
void gemm_bf16(const bf16* __restrict__ A, int lda,
               const bf16* __restrict__ B0, const bf16* __restrict__ B1,
               const bf16* __restrict__ B2, int ldb, int K,
               const float* __restrict__ bias0, const float* __restrict__ bias1,
               const float* __restrict__ bias2,
               const float* __restrict__ resid, int ldr,
               float* __restrict__ Cf,
               bf16* __restrict__ Cb0, bf16* __restrict__ Cb1,
               bf16* __restrict__ Cb2, int ldc)
{
    const int z = blockIdx.z;
    const bf16* B = (z == 0) ? B0 : (z == 1) ? B1 : B2;
    const float* bias = (z == 0) ? bias0 : (z == 1) ? bias1 : bias2;
    bf16* Cb = (z == 0) ? Cb0 : (z == 1) ? Cb1 : Cb2;

    __shared__ bf16 As[128][40];
    __shared__ bf16 Bs[128][40];

    const int tid = threadIdx.x;
    const int lane = tid & 31, wid = tid >> 5;
    const int g = lane >> 2, t = lane & 3;
    const int wm = wid >> 2, wn = wid & 3;
    const int rm = wm * 64, rn = wn * 32;
    const int m0 = blockIdx.y * 128, n0 = blockIdx.x * 128;

    const unsigned Abase = sptr(&As[0][0]) +
        ((rm + (lane & 15)) * 40 + (lane >> 4) * 8) * 2;
    const unsigned Bbase = sptr(&Bs[0][0]) +
        ((rn + (lane & 7)) * 40 + ((lane >> 3) & 1) * 8) * 2;

    float acc[4][4][4];
#pragma unroll
    for (int a = 0; a < 4; a++)
#pragma unroll
        for (int b = 0; b < 4; b++)
#pragma unroll
            for (int c = 0; c < 4; c++) acc[a][b][c] = 0.f;

    const int nk = K / 32;
    uint4 pa[2], pb[2];
#pragma unroll
    for (int r = 0; r < 2; r++) {
        int idx = tid + 256 * r;
        int row = idx >> 2, c = idx & 3;
        pa[r] = *(const uint4*)&A[(size_t)(m0 + row) * lda + c * 8];
        pb[r] = *(const uint4*)&B[(size_t)(n0 + row) * ldb + c * 8];
    }

    for (int kt = 0; kt < nk; kt++) {
#pragma unroll
        for (int r = 0; r < 2; r++) {
            int idx = tid + 256 * r;
            int row = idx >> 2, c = idx & 3;
            *(uint4*)&As[row][c * 8] = pa[r];
            *(uint4*)&Bs[row][c * 8] = pb[r];
        }
        __syncthreads();
        if (kt + 1 < nk) {
            int k0 = (kt + 1) * 32;
#pragma unroll
            for (int r = 0; r < 2; r++) {
                int idx = tid + 256 * r;
                int row = idx >> 2, c = idx & 3;
                pa[r] = *(const uint4*)&A[(size_t)(m0 + row) * lda + k0 + c * 8];
                pb[r] = *(const uint4*)&B[(size_t)(n0 + row) * ldb + k0 + c * 8];
            }
        }
#pragma unroll
        for (int ks = 0; ks < 2; ks++) {
            unsigned afr[4][4];
#pragma unroll
            for (int mf = 0; mf < 4; mf++)
                ldsm4(afr[mf], Abase + mf * 1280 + ks * 32);
#pragma unroll
            for (int nf = 0; nf < 4; nf++) {
                unsigned b0, b1;
                ldsm2(b0, b1, Bbase + nf * 640 + ks * 32);
#pragma unroll
                for (int mf = 0; mf < 4; mf++)
                    mma16816(acc[mf][nf], afr[mf], b0, b1);
            }
        }
        __syncthreads();
    }

#pragma unroll
    for (int mf = 0; mf < 4; mf++) {
        const int m = m0 + rm + mf * 16 + g;
#pragma unroll
        for (int nf = 0; nf < 4; nf++) {
            const int n = n0 + rn + nf * 8 + 2 * t;
            float2 bb = *(const float2*)&bias[n];
            float v0 = acc[mf][nf][0] + bb.x;
            float v1 = acc[mf][nf][1] + bb.y;
            float v2 = acc[mf][nf][2] + bb.x;
            float v3 = acc[mf][nf][3] + bb.y;
            if (Cf) {
                float2 r0 = *(const float2*)&resid[(size_t)m * ldr + n];
                float2 r1 = *(const float2*)&resid[(size_t)(m + 8) * ldr + n];
                *(float2*)&Cf[(size_t)m * ldc + n] = make_float2(v0 + r0.x, v1 + r0.y);
                *(float2*)&Cf[(size_t)(m + 8) * ldc + n] = make_float2(v2 + r1.x, v3 + r1.y);
            } else {
                *(unsigned*)&Cb[(size_t)m * ldc + n] = pack_bf16(v0, v1);
                *(unsigned*)&Cb[(size_t)(m + 8) * ldc + n] = pack_bf16(v2, v3);
            }
        }
    }
}

// ---------------------------------------------------------------------------
// Flash attention, no-max softmax, P-in-registers, cp.async double buffer.
// grid = (NH, S/64), block = 128 (4 warps x 16 q-rows).
// ---------------------------------------------------------------------------
__global__ __launch_bounds__(128)
void attn_mma(const bf16* __restrict__ qkv,
              const float* __restrict__ contact,
              const float* __restrict__ Wc,
              bf16* __restrict__ O)
{
    __shared__ bf16 Qs[64 * 72];
    __shared__ bf16 KVs[2][2][64 * 72];   // [buf][K|V]

    const int tid = threadIdx.x;
    const int lane = tid & 31, wid = tid >> 5;
    const int g = lane >> 2, t = lane & 3;
    const int h = blockIdx.x;
    const int q0 = blockIdx.y * 64;
    const int wr0 = wid * 16;

    const bf16* Qp = qkv;
    const bf16* Kp = qkv + (size_t)S_LEN * NODE;
    const bf16* Vp = qkv + 2 * (size_t)S_LEN * NODE;
    const float scale = 0.125f * 1.44269504f * Wc[h];

    // Q fill (regular stores; covered by first barrier)
#pragma unroll
    for (int r = 0; r < 4; r++) {
        int idx = tid + 128 * r;
        int row = idx >> 3, c = idx & 7;
        *(uint4*)&Qs[row * 72 + c * 8] =
            *(const uint4*)&Qp[(size_t)(q0 + row) * NODE + h * HD + c * 8];
    }

    const int krow = tid >> 3;          // (with +128r) covers 64 rows
    const int kc = (tid & 7) * 8;
    // initial K/V load for kb=0 into buf 0
#pragma unroll
    for (int r = 0; r < 4; r++) {
        int key = krow + 16 * r;
        cpasync16(sptr(&KVs[0][0][key * 72 + kc]),
                  &Kp[(size_t)key * NODE + h * HD + kc]);
        cpasync16(sptr(&KVs[0][1][key * 72 + kc]),
                  &Vp[(size_t)key * NODE + h * HD + kc]);
    }
    cpcommit();

    float l0 = 0.f, l1 = 0.f;
    float oc[8][4];
#pragma unroll
    for (int nf = 0; nf < 8; nf++)
#pragma unroll
        for (int j = 0; j < 4; j++) oc[nf][j] = 0.f;

    const unsigned qAddr = sptr(Qs) +
        ((wr0 + (lane & 15)) * 72 + (lane >> 4) * 8) * 2;

    for (int kb = 0; kb < NKB; kb++) {
        const int buf = kb & 1;
        cpwait0();
        __syncthreads();

        if (kb + 1 < NKB) {
            const int nk0 = (kb + 1) * 64;
            const int nb = buf ^ 1;
#pragma unroll
            for (int r = 0; r < 4; r++) {
                int key = krow + 16 * r;
                cpasync16(sptr(&KVs[nb][0][key * 72 + kc]),
                          &Kp[(size_t)(nk0 + key) * NODE + h * HD + kc]);
                cpasync16(sptr(&KVs[nb][1][key * 72 + kc]),
                          &Vp[(size_t)(nk0 + key) * NODE + h * HD + kc]);
            }
            cpcommit();
        }

        const unsigned Kb = sptr(&KVs[buf][0][0]);
        const unsigned Vb = sptr(&KVs[buf][1][0]);
        const unsigned kAddr = Kb +
            (((lane & 7)) * 72 + ((lane >> 3) & 1) * 8) * 2;
        const unsigned vAddr = Vb + ((lane & 15) * 72) * 2;

        // contact loads (issued early, consumed after QK)
        const int k0 = kb * 64;
        const float* cr0 = contact + (size_t)(q0 + wr0 + g) * S_LEN + k0 + 2 * t;
        const float* cr1 = cr0 + 8 * (size_t)S_LEN;
        float2 c0f[8], c1f[8];
#pragma unroll
        for (int nf = 0; nf < 8; nf++) {
            c0f[nf] = *(const float2*)&cr0[nf * 8];
            c1f[nf] = *(const float2*)&cr1[nf * 8];
        }

        // ---- S = Q K^T ----
        float sc[8][4];
#pragma unroll
        for (int nf = 0; nf < 8; nf++)
#pragma unroll
            for (int j = 0; j < 4; j++) sc[nf][j] = 0.f;
#pragma unroll
        for (int ks = 0; ks < 4; ks++) {
            unsigned afr[4];
            ldsm4(afr, qAddr + ks * 32);
#pragma unroll
            for (int nf = 0; nf < 8; nf++) {
                unsigned b0, b1;
                ldsm2(b0, b1, kAddr + nf * 1152 + ks * 32);
                mma16816(sc[nf], afr, b0, b1);
            }
        }

        // ---- exp (no max subtraction) + row sums + pack to bf16 ----
        unsigned pk[8][2];
        float rs0 = 0.f, rs1 = 0.f;
#pragma unroll
        for (int nf = 0; nf < 8; nf++) {
            float e0 = ex2(fminf(sc[nf][0] * (c0f[nf].x * scale), 30.f));
            float e1 = ex2(fminf(sc[nf][1] * (c0f[nf].y * scale), 30.f));
            float e2 = ex2(fminf(sc[nf][2] * (c1f[nf].x * scale), 30.f));
            float e3 = ex2(fminf(sc[nf][3] * (c1f[nf].y * scale), 30.f));
            rs0 += e0 + e1;
            rs1 += e2 + e3;
            pk[nf][0] = pack_bf16(e0, e1);
            pk[nf][1] = pack_bf16(e2, e3);
        }
        rs0 += __shfl_xor_sync(0xffffffffu, rs0, 1);
        rs0 += __shfl_xor_sync(0xffffffffu, rs0, 2);
        rs1 += __shfl_xor_sync(0xffffffffu, rs1, 1);
        rs1 += __shfl_xor_sync(0xffffffffu, rs1, 2);
        l0 += rs0;
        l1 += rs1;

        // ---- O += P V (A from registers, B via ldmatrix.trans) ----
#pragma unroll
        for (int ks = 0; ks < 4; ks++) {
            unsigned a[4] = { pk[2 * ks][0], pk[2 * ks][1],
                              pk[2 * ks + 1][0], pk[2 * ks + 1][1] };
#pragma unroll
            for (int nf = 0; nf < 8; nf++) {
                unsigned b0, b1;
                ldsm2t(b0, b1, vAddr + ks * 2304 + nf * 16);
                mma16816(oc[nf], a, b0, b1);
            }
        }
    }

    // ---- normalize + store flat [H][S][D] bf16 ----
    const float inv0 = 1.f / l0;
    const float inv1 = 1.f / l1;
    const size_t ob = (size_t)h * S_LEN * HD;
#pragma unroll
    for (int nf = 0; nf < 8; nf++) {
        int col = nf * 8 + 2 * t;
        *(unsigned*)&O[ob + (size_t)(q0 + wr0 + g) * HD + col] =
            pack_bf16(oc[nf][0] * inv0, oc[nf][1] * inv0);
        *(unsigned*)&O[ob + (size_t)(q0 + wr0 + 8 + g) * HD + col] =
            pack_bf16(oc[nf][2] * inv1, oc[nf][3] * inv1);
    }
}

// ---------------------------------------------------------------------------
__global__ __launch_bounds__(256)
void ln_kernel(const float* __restrict__ x,
               const float* __restrict__ gamma,
               const float* __restrict__ beta,
               float* __restrict__ out)
{
    __shared__ float red[16];
    const int row = blockIdx.x;
    const int tid = threadIdx.x;
    const float* xr = x + (size_t)row * NODE;
    float2 v = *(const float2*)&xr[tid * 2];

    float ssum = v.x + v.y;
#pragma unroll
    for (int off = 16; off >= 1; off >>= 1)
        ssum += __shfl_xor_sync(0xffffffffu, ssum, off);
    if ((tid & 31) == 0) red[tid >> 5] = ssum;
    __syncthreads();
    float tot = 0.f;
#pragma unroll
    for (int w = 0; w < 8; w++) tot += red[w];
    const float mean = tot * (1.f / NODE);

    const float dx = v.x - mean, dy = v.y - mean;
    float sq = dx * dx + dy * dy;
#pragma unroll
    for (int off = 16; off >= 1; off >>= 1)
        sq += __shfl_xor_sync(0xffffffffu, sq, off);
    if ((tid & 31) == 0) red[8 + (tid >> 5)] = sq;
    __syncthreads();
    float tot2 = 0.f;
#pragma unroll
    for (int w = 0; w < 8; w++) tot2 += red[8 + w];
    const float inv = rsqrtf(tot2 * (1.f / NODE) + 1e-5f);

    const int n = tid * 2;
    float2 gm = *(const float2*)&gamma[n];
    float2 bt = *(const float2*)&beta[n];
    float2 o;
    o.x = dx * inv * gm.x + bt.x;
    o.y = dy * inv * gm.y + bt.y;
    *(float2*)&out[(size_t)row * NODE + n] = o;
}

// ---------------------------------------------------------------------------
extern "C" void kernel_launch(void* const* d_in, const int* in_sizes, int n_in,
                              void* d_out, int out_size)
{
    const float* X     = (const float*)d_in[0];
    const float* Ct    = (const float*)d_in[1];
    const float* Wq    = (const float*)d_in[2];
    const float* bq    = (const float*)d_in[3];
    const float* Wk    = (const float*)d_in[4];
    const float* bk    = (const float*)d_in[5];
    const float* Wv    = (const float*)d_in[6];
    const float* bv    = (const float*)d_in[7];
    const float* Wc    = (const float*)d_in[8];
    const float* Wo    = (const float*)d_in[9];
    const float* bo    = (const float*)d_in[10];
    const float* gamma = (const float*)d_in[11];
    const float* beta  = (const float*)d_in[12];
    float* out = (float*)d_out;

    void *pX, *pWq, *pWk, *pWv, *pWo, *pQKV, *pO, *pAug;
    cudaGetSymbolAddress(&pX, g_Xbf);
    cudaGetSymbolAddress(&pWq, g_Wqb);
    cudaGetSymbolAddress(&pWk, g_Wkb);
    cudaGetSymbolAddress(&pWv, g_Wvb);
    cudaGetSymbolAddress(&pWo, g_Wob);
    cudaGetSymbolAddress(&pQKV, g_QKVb);
    cudaGetSymbolAddress(&pO, g_Obf);
    cudaGetSymbolAddress(&pAug, g_aug);
    bf16* Xbf = (bf16*)pX;
    bf16* Wqb = (bf16*)pWq;
    bf16* Wkb = (bf16*)pWk;
    bf16* Wvb = (bf16*)pWv;
    bf16* Wob = (bf16*)pWo;
    bf16* qkv = (bf16*)pQKV;
    bf16* Obf = (bf16*)pO;
    float* aug = (float*)pAug;

    // 1. all fp32 -> bf16 conversions in one launch
    cvt_all<<<5888, 256>>>(X, Wq, Wk, Wv, Wo, Xbf, Wqb, Wkb, Wvb, Wob);

    // 2. fused QKV projection
    gemm_bf16<<<dim3(NODE / 128, S_LEN / 128, 3), 256>>>(
        Xbf, IN_DIM, Wqb, Wkb, Wvb, IN_DIM, IN_DIM,
        bq, bk, bv, nullptr, 0, nullptr,
        qkv, qkv + (size_t)S_LEN * NODE, qkv + 2 * (size_t)S_LEN * NODE, NODE);

    // 3. flash attention (head-major grid for contact L2 reuse)
    attn_mma<<<dim3(NH, S_LEN / 64), 128>>>(qkv, Ct, Wc, Obf);

    // 4. output projection + bias + residual (fp32)
    gemm_bf16<<<dim3(NODE / 128, S_LEN / 128, 1), 256>>>(
        Obf, NODE, Wob, Wob, Wob, NODE, NODE,
        bo, bo, bo, X, IN_DIM, aug,
        nullptr, nullptr, nullptr, NODE);

    // 5. LayerNorm
    ln_kernel<<<S_LEN, 256>>>(aug, gamma, beta, out);
}

// round 7
// speedup vs baseline: 7.9988x; 1.1595x over previous
#include <cuda_runtime.h>
#include <cuda_bf16.h>
#include <math.h>
#include <stdint.h>

#define S_LEN 4096
#define IN_DIM 1024
#define NODE 512
#define NH 8
#define HD 64
#define NKB (S_LEN / 64)

typedef __nv_bfloat16 bf16;

// ---------------- device scratch ----------------
__device__ bf16  g_Xbf[S_LEN * IN_DIM];
__device__ bf16  g_Wqb[NODE * IN_DIM];
__device__ bf16  g_Wkb[NODE * IN_DIM];
__device__ bf16  g_Wvb[NODE * IN_DIM];
__device__ bf16  g_Wob[NODE * NODE];
__device__ bf16  g_QKVb[3 * S_LEN * NODE];
__device__ bf16  g_Obf[NH * S_LEN * HD];
__device__ float g_aug[S_LEN * NODE];

// ---------------- helpers ----------------
__device__ __forceinline__ void mma16816(float c[4], const unsigned a[4],
                                         unsigned b0, unsigned b1) {
    asm volatile(
        "mma.sync.aligned.m16n8k16.row.col.f32.bf16.bf16.f32 "
        "{%0,%1,%2,%3}, {%4,%5,%6,%7}, {%8,%9}, {%0,%1,%2,%3};\n"
        : "+f"(c[0]), "+f"(c[1]), "+f"(c[2]), "+f"(c[3])
        : "r"(a[0]), "r"(a[1]), "r"(a[2]), "r"(a[3]), "r"(b0), "r"(b1));
}
__device__ __forceinline__ unsigned pack_bf16(float x, float y) {
    unsigned r;
    asm("cvt.rn.bf16x2.f32 %0, %1, %2;" : "=r"(r) : "f"(y), "f"(x));
    return r;
}
__device__ __forceinline__ float ex2(float x) {
    float y;
    asm("ex2.approx.f32 %0, %1;" : "=f"(y) : "f"(x));
    return y;
}
__device__ __forceinline__ unsigned sptr(const void* p) {
    return (unsigned)__cvta_generic_to_shared(p);
}
__device__ __forceinline__ void ldsm4(unsigned r[4], unsigned a) {
    asm volatile("ldmatrix.sync.aligned.m8n8.x4.shared.b16 {%0,%1,%2,%3}, [%4];\n"
                 : "=r"(r[0]), "=r"(r[1]), "=r"(r[2]), "=r"(r[3]) : "r"(a));
}
__device__ __forceinline__ void ldsm2(unsigned& r0, unsigned& r1, unsigned a) {
    asm volatile("ldmatrix.sync.aligned.m8n8.x2.shared.b16 {%0,%1}, [%2];\n"
                 : "=r"(r0), "=r"(r1) : "r"(a));
}
__device__ __forceinline__ void ldsm2t(unsigned& r0, unsigned& r1, unsigned a) {
    asm volatile("ldmatrix.sync.aligned.m8n8.x2.trans.shared.b16 {%0,%1}, [%2];\n"
                 : "=r"(r0), "=r"(r1) : "r"(a));
}
__device__ __forceinline__ void cpasync16(unsigned saddr, const void* g) {
    asm volatile("cp.async.cg.shared.global [%0], [%1], 16;\n"
                 :: "r"(saddr), "l"(g));
}
__device__ __forceinline__ void cpcommit() {
    asm volatile("cp.async.commit_group;\n");
}
template <int N>
__device__ __forceinline__ void cpwaitg() {
    asm volatile("cp.async.wait_group %0;\n" :: "n"(N));
}

// ---------------------------------------------------------------------------
// fused fp32 -> bf16 conversions
// ---------------------------------------------------------------------------
__global__ __launch_bounds__(256)
void cvt_all(const float* __restrict__ X, const float* __restrict__ Wq,
             const float* __restrict__ Wk, const float* __restrict__ Wv,
             const float* __restrict__ Wo,
             bf16* dX, bf16* dWq, bf16* dWk, bf16* dWv, bf16* dWo)
{
    int b = blockIdx.x;
    const float* s; bf16* d; int off;
    if (b < 4096)      { s = X;  d = dX;  off = b; }
    else if (b < 4608) { s = Wq; d = dWq; off = b - 4096; }
    else if (b < 5120) { s = Wk; d = dWk; off = b - 4608; }
    else if (b < 5632) { s = Wv; d = dWv; off = b - 5120; }
    else               { s = Wo; d = dWo; off = b - 5632; }
    int i = (off * 256 + threadIdx.x) * 4;
    float4 v = *(const float4*)&s[i];
    uint2 o;
    o.x = pack_bf16(v.x, v.y);
    o.y = pack_bf16(v.z, v.w);
    *(uint2*)&d[i] = o;
}

// ---------------------------------------------------------------------------
// bf16 tensor-core GEMM, cp.async double-buffered.
// C[M,N] = A[M,K] @ B[N,K]^T + bias (+resid). 128x128, BK=32, 256 thr.
// Fill: each thread copies rows frow and frow+64 (16B each) per matrix.
// ---------------------------------------------------------------------------
__global__ __launch_bounds__(256, 2)
void gemm_bf16(const bf16* __restrict__ A, int lda,
               const bf16* __restrict__ B0, const bf16* __restrict__ B1,
               const bf16* __restrict__ B2, int ldb, int K,
               const float* __restrict__ bias0, const float* __restrict__ bias1,
               const float* __restrict__ bias2,
               const float* __restrict__ resid, int ldr,
               float* __restrict__ Cf,
               bf16* __restrict__ Cb0, bf16* __restrict__ Cb1,
               bf16* __restrict__ Cb2, int ldc)
{
    const int z = blockIdx.z;
    const bf16* B = (z == 0) ? B0 : (z == 1) ? B1 : B2;
    const float* bias = (z == 0) ? bias0 : (z == 1) ? bias1 : bias2;
    bf16* Cb = (z == 0) ? Cb0 : (z == 1) ? Cb1 : Cb2;

    __shared__ bf16 As[2][128][40];
    __shared__ bf16 Bs[2][128][40];

    const int tid = threadIdx.x;
    const int lane = tid & 31, wid = tid >> 5;
    const int g = lane >> 2, t = lane & 3;
    const int wm = wid >> 2, wn = wid & 3;
    const int rm = wm * 64, rn = wn * 32;
    const int m0 = blockIdx.y * 128, n0 = blockIdx.x * 128;

    const int frow = tid >> 2, fcol = (tid & 3) * 8;   // rows frow, frow+64
    const bf16* Ag0 = A + (size_t)(m0 + frow) * lda + fcol;
    const bf16* Ag1 = A + (size_t)(m0 + frow + 64) * lda + fcol;
    const bf16* Bg0 = B + (size_t)(n0 + frow) * ldb + fcol;
    const bf16* Bg1 = B + (size_t)(n0 + frow + 64) * ldb + fcol;

    float acc[4][4][4];
#pragma unroll
    for (int a = 0; a < 4; a++)
#pragma unroll
        for (int b = 0; b < 4; b++)
#pragma unroll
            for (int c = 0; c < 4; c++) acc[a][b][c] = 0.f;

    const int nk = K / 32;
    // prologue: tiles 0 and 1
    cpasync16(sptr(&As[0][frow][fcol]), Ag0);
    cpasync16(sptr(&As[0][frow + 64][fcol]), Ag1);
    cpasync16(sptr(&Bs[0][frow][fcol]), Bg0);
    cpasync16(sptr(&Bs[0][frow + 64][fcol]), Bg1);
    cpcommit();
    if (nk > 1) {
        cpasync16(sptr(&As[1][frow][fcol]), Ag0 + 32);
        cpasync16(sptr(&As[1][frow + 64][fcol]), Ag1 + 32);
        cpasync16(sptr(&Bs[1][frow][fcol]), Bg0 + 32);
        cpasync16(sptr(&Bs[1][frow + 64][fcol]), Bg1 + 32);
    }
    cpcommit();

    for (int kt = 0; kt < nk; kt++) {
        const int buf = kt & 1;
        if (kt + 1 < nk) cpwaitg<1>(); else cpwaitg<0>();
        __syncthreads();

        const unsigned Abase = sptr(&As[buf][0][0]) +
            ((rm + (lane & 15)) * 40 + (lane >> 4) * 8) * 2;
        const unsigned Bbase = sptr(&Bs[buf][0][0]) +
            ((rn + (lane & 7)) * 40 + ((lane >> 3) & 1) * 8) * 2;
#pragma unroll
        for (int ks = 0; ks < 2; ks++) {
            unsigned afr[4][4];
#pragma unroll
            for (int mf = 0; mf < 4; mf++)
                ldsm4(afr[mf], Abase + mf * 1280 + ks * 32);
#pragma unroll
            for (int nf = 0; nf < 4; nf++) {
                unsigned b0, b1;
                ldsm2(b0, b1, Bbase + nf * 640 + ks * 32);
#pragma unroll
                for (int mf = 0; mf < 4; mf++)
                    mma16816(acc[mf][nf], afr[mf], b0, b1);
            }
        }
        __syncthreads();
        if (kt + 2 < nk) {
            const int ko = (kt + 2) * 32;
            cpasync16(sptr(&As[buf][frow][fcol]), Ag0 + ko);
            cpasync16(sptr(&As[buf][frow + 64][fcol]), Ag1 + ko);
            cpasync16(sptr(&Bs[buf][frow][fcol]), Bg0 + ko);
            cpasync16(sptr(&Bs[buf][frow + 64][fcol]), Bg1 + ko);
        }
        cpcommit();
    }

#pragma unroll
    for (int mf = 0; mf < 4; mf++) {
        const int m = m0 + rm + mf * 16 + g;
#pragma unroll
        for (int nf = 0; nf < 4; nf++) {
            const int n = n0 + rn + nf * 8 + 2 * t;
            float2 bb = *(const float2*)&bias[n];
            float v0 = acc[mf][nf][0] + bb.x;
            float v1 = acc[mf][nf][1] + bb.y;
            float v2 = acc[mf][nf][2] + bb.x;
            float v3 = acc[mf][nf][3] + bb.y;
            if (Cf) {
                float2 r0 = *(const float2*)&resid[(size_t)m * ldr + n];
                float2 r1 = *(const float2*)&resid[(size_t)(m + 8) * ldr + n];
                *(float2*)&Cf[(size_t)m * ldc + n] = make_float2(v0 + r0.x, v1 + r0.y);
                *(float2*)&Cf[(size_t)(m + 8) * ldc + n] = make_float2(v2 + r1.x, v3 + r1.y);
            } else {
                *(unsigned*)&Cb[(size_t)m * ldc + n] = pack_bf16(v0, v1);
                *(unsigned*)&Cb[(size_t)(m + 8) * ldc + n] = pack_bf16(v2, v3);
            }
        }
    }
}

// ---------------------------------------------------------------------------
// Flash attention: 128 q-rows/CTA, 4 warps x 32 rows (2 m-tiles), no-max
// softmax, P in registers, Q frags hoisted, cp.async double-buffered K/V.
// grid = (NH, S/128), block = 128.
// ---------------------------------------------------------------------------
__global__ __launch_bounds__(128, 2)
void attn_mma(const bf16* __restrict__ qkv,
              const float* __restrict__ contact,
              const float* __restrict__ Wc,
              bf16* __restrict__ O)
{
    extern __shared__ bf16 sm[];
    bf16* Qs = sm;                        // [128][72]
    bf16* KVs = sm + 128 * 72;            // [2 buf][K|V][64*72]

    const int tid = threadIdx.x;
    const int lane = tid & 31, wid = tid >> 5;
    const int g = lane >> 2, t = lane & 3;
    const int h = blockIdx.x;
    const int q0 = blockIdx.y * 128;
    const int wr0 = wid * 32;

    const bf16* Qp = qkv;
    const bf16* Kp = qkv + (size_t)S_LEN * NODE;
    const bf16* Vp = qkv + 2 * (size_t)S_LEN * NODE;
    const float scale = 0.125f * 1.44269504f * Wc[h];

    const int frow = tid >> 3, fcol = (tid & 7) * 8;

    // ---- Q + K/V blocks 0,1 (cp.async) ----
#pragma unroll
    for (int r = 0; r < 8; r++) {
        int row = frow + 16 * r;
        cpasync16(sptr(&Qs[row * 72 + fcol]),
                  &Qp[(size_t)(q0 + row) * NODE + h * HD + fcol]);
    }
#pragma unroll
    for (int r = 0; r < 4; r++) {
        int row = frow + 16 * r;
        cpasync16(sptr(&KVs[row * 72 + fcol]),
                  &Kp[(size_t)row * NODE + h * HD + fcol]);
        cpasync16(sptr(&KVs[64 * 72 + row * 72 + fcol]),
                  &Vp[(size_t)row * NODE + h * HD + fcol]);
    }
    cpcommit();
#pragma unroll
    for (int r = 0; r < 4; r++) {
        int row = frow + 16 * r;
        cpasync16(sptr(&KVs[2 * 64 * 72 + row * 72 + fcol]),
                  &Kp[(size_t)(64 + row) * NODE + h * HD + fcol]);
        cpasync16(sptr(&KVs[3 * 64 * 72 + row * 72 + fcol]),
                  &Vp[(size_t)(64 + row) * NODE + h * HD + fcol]);
    }
    cpcommit();

    cpwaitg<1>();
    __syncthreads();

    // ---- hoist Q fragments (loop-invariant) ----
    unsigned qf[2][4][4];
#pragma unroll
    for (int mt = 0; mt < 2; mt++) {
        const unsigned qa = sptr(Qs) +
            ((wr0 + mt * 16 + (lane & 15)) * 72 + (lane >> 4) * 8) * 2;
#pragma unroll
        for (int ks = 0; ks < 4; ks++)
            ldsm4(qf[mt][ks], qa + ks * 32);
    }

    float oc[2][8][4];
#pragma unroll
    for (int mt = 0; mt < 2; mt++)
#pragma unroll
        for (int nf = 0; nf < 8; nf++)
#pragma unroll
            for (int j = 0; j < 4; j++) oc[mt][nf][j] = 0.f;
    float lacc[2][2] = {{0.f, 0.f}, {0.f, 0.f}};

    const float* cbase = contact + (size_t)(q0 + wr0 + g) * S_LEN + 2 * t;

    for (int kb = 0; kb < NKB; kb++) {
        const int buf = kb & 1;
        if (kb > 0) {
            if (kb + 1 < NKB) cpwaitg<1>(); else cpwaitg<0>();
            __syncthreads();
        }

        const bf16* Kb = KVs + buf * (2 * 64 * 72);
        const unsigned kAddr = sptr(Kb) +
            ((lane & 7) * 72 + ((lane >> 3) & 1) * 8) * 2;
        const unsigned vAddr = sptr(Kb + 64 * 72) + ((lane & 15) * 72) * 2;
        const float* cp0 = cbase + (size_t)kb * 64;

        // ---- QK + exp + pack, nf-outer ----
        unsigned pk[2][8][2];
#pragma unroll
        for (int nf = 0; nf < 8; nf++) {
            unsigned kb0[4], kb1[4];
#pragma unroll
            for (int ks = 0; ks < 4; ks++)
                ldsm2(kb0[ks], kb1[ks], kAddr + nf * 1152 + ks * 32);
            float s0[4] = {0.f, 0.f, 0.f, 0.f};
            float s1[4] = {0.f, 0.f, 0.f, 0.f};
#pragma unroll
            for (int ks = 0; ks < 4; ks++) {
                mma16816(s0, qf[0][ks], kb0[ks], kb1[ks]);
                mma16816(s1, qf[1][ks], kb0[ks], kb1[ks]);
            }
            float2 c00 = *(const float2*)&cp0[nf * 8];
            float2 c01 = *(const float2*)&cp0[8 * S_LEN + nf * 8];
            float2 c10 = *(const float2*)&cp0[16 * (size_t)S_LEN + nf * 8];
            float2 c11 = *(const float2*)&cp0[24 * (size_t)S_LEN + nf * 8];
            float e0 = ex2(s0[0] * (c00.x * scale));
            float e1 = ex2(s0[1] * (c00.y * scale));
            float e2 = ex2(s0[2] * (c01.x * scale));
            float e3 = ex2(s0[3] * (c01.y * scale));
            lacc[0][0] += e0 + e1;
            lacc[0][1] += e2 + e3;
            pk[0][nf][0] = pack_bf16(e0, e1);
            pk[0][nf][1] = pack_bf16(e2, e3);
            float f0 = ex2(s1[0] * (c10.x * scale));
            float f1 = ex2(s1[1] * (c10.y * scale));
            float f2 = ex2(s1[2] * (c11.x * scale));
            float f3 = ex2(s1[3] * (c11.y * scale));
            lacc[1][0] += f0 + f1;
            lacc[1][1] += f2 + f3;
            pk[1][nf][0] = pack_bf16(f0, f1);
            pk[1][nf][1] = pack_bf16(f2, f3);
        }

        // ---- O += P V ----
#pragma unroll
        for (int ks = 0; ks < 4; ks++) {
            unsigned a0[4] = { pk[0][2 * ks][0], pk[0][2 * ks][1],
                               pk[0][2 * ks + 1][0], pk[0][2 * ks + 1][1] };
            unsigned a1[4] = { pk[1][2 * ks][0], pk[1][2 * ks][1],
                               pk[1][2 * ks + 1][0], pk[1][2 * ks + 1][1] };
#pragma unroll
            for (int nf = 0; nf < 8; nf++) {
                unsigned b0, b1;
                ldsm2t(b0, b1, vAddr + ks * 2304 + nf * 16);
                mma16816(oc[0][nf], a0, b0, b1);
                mma16816(oc[1][nf], a1, b0, b1);
            }
        }

        __syncthreads();
        if (kb + 2 < NKB) {
            const size_t gr = (size_t)(kb + 2) * 64;
            bf16* dK = KVs + buf * (2 * 64 * 72);
#pragma unroll
            for (int r = 0; r < 4; r++) {
                int row = frow + 16 * r;
                cpasync16(sptr(&dK[row * 72 + fcol]),
                          &Kp[(gr + row) * NODE + h * HD + fcol]);
                cpasync16(sptr(&dK[64 * 72 + row * 72 + fcol]),
                          &Vp[(gr + row) * NODE + h * HD + fcol]);
            }
        }
        cpcommit();
    }

    // ---- normalize + store flat [H][S][D] bf16 ----
#pragma unroll
    for (int mt = 0; mt < 2; mt++) {
        float la = lacc[mt][0], lb = lacc[mt][1];
        la += __shfl_xor_sync(0xffffffffu, la, 1);
        la += __shfl_xor_sync(0xffffffffu, la, 2);
        lb += __shfl_xor_sync(0xffffffffu, lb, 1);
        lb += __shfl_xor_sync(0xffffffffu, lb, 2);
        const float inv0 = 1.f / la;
        const float inv1 = 1.f / lb;
        bf16* dst0 = O + (size_t)h * S_LEN * HD +
                     (size_t)(q0 + wr0 + mt * 16 + g) * HD;
        bf16* dst1 = dst0 + 8 * HD;
#pragma unroll
        for (int nf = 0; nf < 8; nf++) {
            int col = nf * 8 + 2 * t;
            *(unsigned*)&dst0[col] =
                pack_bf16(oc[mt][nf][0] * inv0, oc[mt][nf][1] * inv0);
            *(unsigned*)&dst1[col] =
                pack_bf16(oc[mt][nf][2] * inv1, oc[mt][nf][3] * inv1);
        }
    }
}

// ---------------------------------------------------------------------------
__global__ __launch_bounds__(256)
void ln_kernel(const float* __restrict__ x,
               const float* __restrict__ gamma,
               const float* __restrict__ beta,
               float* __restrict__ out)
{
    __shared__ float red[16];
    const int row = blockIdx.x;
    const int tid = threadIdx.x;
    const float* xr = x + (size_t)row * NODE;
    float2 v = *(const float2*)&xr[tid * 2];

    float ssum = v.x + v.y;
#pragma unroll
    for (int off = 16; off >= 1; off >>= 1)
        ssum += __shfl_xor_sync(0xffffffffu, ssum, off);
    if ((tid & 31) == 0) red[tid >> 5] = ssum;
    __syncthreads();
    float tot = 0.f;
#pragma unroll
    for (int w = 0; w < 8; w++) tot += red[w];
    const float mean = tot * (1.f / NODE);

    const float dx = v.x - mean, dy = v.y - mean;
    float sq = dx * dx + dy * dy;
#pragma unroll
    for (int off = 16; off >= 1; off >>= 1)
        sq += __shfl_xor_sync(0xffffffffu, sq, off);
    if ((tid & 31) == 0) red[8 + (tid >> 5)] = sq;
    __syncthreads();
    float tot2 = 0.f;
#pragma unroll
    for (int w = 0; w < 8; w++) tot2 += red[8 + w];
    const float inv = rsqrtf(tot2 * (1.f / NODE) + 1e-5f);

    const int n = tid * 2;
    float2 gm = *(const float2*)&gamma[n];
    float2 bt = *(const float2*)&beta[n];
    float2 o;
    o.x = dx * inv * gm.x + bt.x;
    o.y = dy * inv * gm.y + bt.y;
    *(float2*)&out[(size_t)row * NODE + n] = o;
}

// ---------------------------------------------------------------------------
extern "C" void kernel_launch(void* const* d_in, const int* in_sizes, int n_in,
                              void* d_out, int out_size)
{
    const float* X     = (const float*)d_in[0];
    const float* Ct    = (const float*)d_in[1];
    const float* Wq    = (const float*)d_in[2];
    const float* bq    = (const float*)d_in[3];
    const float* Wk    = (const float*)d_in[4];
    const float* bk    = (const float*)d_in[5];
    const float* Wv    = (const float*)d_in[6];
    const float* bv    = (const float*)d_in[7];
    const float* Wc    = (const float*)d_in[8];
    const float* Wo    = (const float*)d_in[9];
    const float* bo    = (const float*)d_in[10];
    const float* gamma = (const float*)d_in[11];
    const float* beta  = (const float*)d_in[12];
    float* out = (float*)d_out;

    void *pX, *pWq, *pWk, *pWv, *pWo, *pQKV, *pO, *pAug;
    cudaGetSymbolAddress(&pX, g_Xbf);
    cudaGetSymbolAddress(&pWq, g_Wqb);
    cudaGetSymbolAddress(&pWk, g_Wkb);
    cudaGetSymbolAddress(&pWv, g_Wvb);
    cudaGetSymbolAddress(&pWo, g_Wob);
    cudaGetSymbolAddress(&pQKV, g_QKVb);
    cudaGetSymbolAddress(&pO, g_Obf);
    cudaGetSymbolAddress(&pAug, g_aug);
    bf16* Xbf = (bf16*)pX;
    bf16* Wqb = (bf16*)pWq;
    bf16* Wkb = (bf16*)pWk;
    bf16* Wvb = (bf16*)pWv;
    bf16* Wob = (bf16*)pWo;
    bf16* qkv = (bf16*)pQKV;
    bf16* Obf = (bf16*)pO;
    float* aug = (float*)pAug;

    // 1. fp32 -> bf16
    cvt_all<<<5888, 256>>>(X, Wq, Wk, Wv, Wo, Xbf, Wqb, Wkb, Wvb, Wob);

    // 2. fused QKV projection
    gemm_bf16<<<dim3(NODE / 128, S_LEN / 128, 3), 256>>>(
        Xbf, IN_DIM, Wqb, Wkb, Wvb, IN_DIM, IN_DIM,
        bq, bk, bv, nullptr, 0, nullptr,
        qkv, qkv + (size_t)S_LEN * NODE, qkv + 2 * (size_t)S_LEN * NODE, NODE);

    // 3. flash attention (head-major grid for contact L2 reuse)
    const int smem_bytes = (128 * 72 + 2 * 2 * 64 * 72) * (int)sizeof(bf16);
    cudaFuncSetAttribute(attn_mma,
                         cudaFuncAttributeMaxDynamicSharedMemorySize,
                         smem_bytes);
    attn_mma<<<dim3(NH, S_LEN / 128), 128, smem_bytes>>>(qkv, Ct, Wc, Obf);

    // 4. output projection + bias + residual
    gemm_bf16<<<dim3(NODE / 128, S_LEN / 128, 1), 256>>>(
        Obf, NODE, Wob, Wob, Wob, NODE, NODE,
        bo, bo, bo, X, IN_DIM, aug,
        nullptr, nullptr, nullptr, NODE);

    // 5. LayerNorm
    ln_kernel<<<S_LEN, 256>>>(aug, gamma, beta, out);
}